// round 11
// baseline (speedup 1.0000x reference)
#include <cuda_runtime.h>
#include <cuda_fp16.h>

#define NN 50000
#define NE 800000
#define ET 850000   // NE + NN self loops
#define DD 64
#define HH 6
#define HD 384      // HH*DD
#define BB 1024
#define KSPLIT 10
#define KPB (NN / KSPLIT)   // 5000 per pool block

// ---- scratch (device globals; no allocation allowed) ----
__device__ uint2 g_xph[NN * 96];     // per-layer transformed features [N,H*D] as fp16 (4 halves per uint2)
__device__ float g_as[NN * HH];
__device__ float g_ad[NN * HH];
__device__ float g_h1[NN * DD];      // layer-0 output
__device__ float g_h2[NN * DD];      // layer-1 output
__device__ float g_pool[BB * DD];
__device__ float g_weff[2 * DD];
__device__ float g_beff;
__device__ int   g_deg[NN];
__device__ int   g_off[NN + 1];
__device__ int   g_cur[NN];
__device__ int   g_srcs[ET];

// packed f32x2 FMA (sm_100+ FFMA2)
__device__ __forceinline__ float2 ffma2(float2 d, float2 a, float2 b) {
    unsigned long long dd = *reinterpret_cast<unsigned long long*>(&d);
    unsigned long long aa = *reinterpret_cast<unsigned long long*>(&a);
    unsigned long long bb = *reinterpret_cast<unsigned long long*>(&b);
    asm("fma.rn.f32x2 %0, %1, %2, %0;" : "+l"(dd) : "l"(aa), "l"(bb));
    return *reinterpret_cast<float2*>(&dd);
}

// ---------------------------------------------------------------- init
__global__ void k_init() {
    int i = blockIdx.x * blockDim.x + threadIdx.x;
    if (i < NN) g_deg[i] = 1;              // self loop
    if (i < BB * DD) g_pool[i] = 0.f;
}

// ---------------------------------------------------------------- histogram of dst
__global__ void k_hist(const int* __restrict__ ei) {
    int e = blockIdx.x * blockDim.x + threadIdx.x;
    if (e < NE) atomicAdd(&g_deg[ei[NE + e]], 1);
}

// ---------------------------------------------------------------- exclusive scan (1 block, warp shuffles)
__global__ void k_scan() {
    const int C = 49;                      // 1024*49 >= NN
    int t = threadIdx.x;
    int base = t * C;
    int v[C];
    int run = 0;
#pragma unroll
    for (int i = 0; i < C; i++) {
        int idx = base + i;
        int d = (idx < NN) ? g_deg[idx] : 0;
        run += d;
        v[i] = run;                        // inclusive within chunk
    }
    int lane = t & 31, wid = t >> 5;
    int x = run;
#pragma unroll
    for (int o = 1; o < 32; o <<= 1) {
        int y = __shfl_up_sync(0xffffffffu, x, o);
        if (lane >= o) x += y;
    }
    __shared__ int wsum[32];
    if (lane == 31) wsum[wid] = x;
    __syncthreads();
    if (wid == 0) {
        int w = wsum[lane];
#pragma unroll
        for (int o = 1; o < 32; o <<= 1) {
            int y = __shfl_up_sync(0xffffffffu, w, o);
            if (lane >= o) w += y;
        }
        wsum[lane] = w;
    }
    __syncthreads();
    int prefix = x - run + (wid ? wsum[wid - 1] : 0);  // exclusive prefix of chunk
    if (t == 0) g_off[0] = 0;
#pragma unroll
    for (int i = 0; i < C; i++) {
        int idx = base + i;
        if (idx < NN) {
            g_off[idx + 1] = prefix + v[i];
            g_cur[idx] = prefix + (i ? v[i - 1] : 0);
        }
    }
}

// ---------------------------------------------------------------- fill CSR (srcs grouped by dst)
__global__ void k_fill(const int* __restrict__ ei) {
    int i = blockIdx.x * blockDim.x + threadIdx.x;
    if (i >= ET) return;
    int s, d;
    if (i < NE) { s = ei[i]; d = ei[NE + i]; }
    else        { s = i - NE; d = s; }
    int pos = atomicAdd(&g_cur[d], 1);
    g_srcs[pos] = s;
}

// ---------------------------------------------------------------- xp = x @ W + fused attention dots
// block: 64 rows x 64 cols; blockIdx.y == head h (cols are exactly head h)
// xp stored as fp16 (only consumer is the attn gather)
__global__ void k_gemm(const float* __restrict__ x_in, const float* __restrict__ W,
                       const float* __restrict__ asrc, const float* __restrict__ adst,
                       int use_h1) {
    __shared__ float AsT[64][68];   // [k][row]
    __shared__ float Bs[64][68];    // [k][col]
    const float* x = use_h1 ? g_h1 : x_in;
    int t = threadIdx.x;
    int row0 = blockIdx.x * 64;
    int h = blockIdx.y;
    int col0 = h * 64;
    {
        int lr = t >> 4, lc = (t & 15) * 4;
#pragma unroll
        for (int r = lr; r < 64; r += 16) {
            int gr = row0 + r;
            float4 v = (gr < NN) ? *(const float4*)(x + (size_t)gr * DD + lc)
                                 : make_float4(0, 0, 0, 0);
            AsT[lc][r] = v.x; AsT[lc + 1][r] = v.y; AsT[lc + 2][r] = v.z; AsT[lc + 3][r] = v.w;
        }
#pragma unroll
        for (int k = lr; k < 64; k += 16) {
            float4 v = *(const float4*)(W + (size_t)k * HD + col0 + lc);
            Bs[k][lc] = v.x; Bs[k][lc + 1] = v.y; Bs[k][lc + 2] = v.z; Bs[k][lc + 3] = v.w;
        }
    }
    __syncthreads();
    int ty = t >> 4, tx = t & 15;
    float2 acc[4][2] = {};
#pragma unroll
    for (int k = 0; k < 64; k++) {
        float4 a4 = *(const float4*)&AsT[k][ty * 4];
        float4 b4 = *(const float4*)&Bs[k][tx * 4];
        float2 b01 = make_float2(b4.x, b4.y), b23 = make_float2(b4.z, b4.w);
        float a[4] = {a4.x, a4.y, a4.z, a4.w};
#pragma unroll
        for (int i = 0; i < 4; i++) {
            float2 ai = make_float2(a[i], a[i]);
            acc[i][0] = ffma2(acc[i][0], ai, b01);
            acc[i][1] = ffma2(acc[i][1], ai, b23);
        }
    }
    // epilogue: write xp (fp16) and fused as/ad dot-products for head h
    float4 sa4 = *(const float4*)(asrc + col0 + tx * 4);
    float4 sd4 = *(const float4*)(adst + col0 + tx * 4);
#pragma unroll
    for (int i = 0; i < 4; i++) {
        int gr = row0 + ty * 4 + i;
        float4 o = make_float4(acc[i][0].x, acc[i][0].y, acc[i][1].x, acc[i][1].y);
        if (gr < NN) {
            __half2 h01 = __floats2half2_rn(o.x, o.y);
            __half2 h23 = __floats2half2_rn(o.z, o.w);
            uint2 u;
            u.x = *reinterpret_cast<unsigned int*>(&h01);
            u.y = *reinterpret_cast<unsigned int*>(&h23);
            g_xph[(size_t)gr * 96 + h * 16 + tx] = u;
        }
        float s1 = o.x * sa4.x + o.y * sa4.y + o.z * sa4.z + o.w * sa4.w;
        float s2 = o.x * sd4.x + o.y * sd4.y + o.z * sd4.z + o.w * sd4.w;
#pragma unroll
        for (int m = 8; m; m >>= 1) {
            s1 += __shfl_xor_sync(0xffffffffu, s1, m);
            s2 += __shfl_xor_sync(0xffffffffu, s2, m);
        }
        if (tx == 0 && gr < NN) { g_as[gr * HH + h] = s1; g_ad[gr * HH + h] = s2; }
    }
}

// unpack 4 halves (uint2) and accumulate with weight w
__device__ __forceinline__ void acc_h4(float4& acc, float w, uint2 v) {
    __half2 a = *reinterpret_cast<__half2*>(&v.x);
    __half2 b = *reinterpret_cast<__half2*>(&v.y);
    float2 f01 = __half22float2(a);
    float2 f23 = __half22float2(b);
    acc.x += w * f01.x; acc.y += w * f01.y;
    acc.z += w * f23.x; acc.w += w * f23.y;
}

__device__ __forceinline__ float leaky_exp(float e) {
    e = (e > 0.f) ? e : 0.2f * e;
    return __expf(e);
}

// ---------------------------------------------------------------- attention: warp per dst node, SINGLE PASS
// softmax shift-invariance (no max) + post-normalization:
//   out = (sum_i p_i x_i) / (sum_i p_i),  p_i computed in-register, no g_p array
// Each half-warp (hsel = lane>>4) handles heads {hsel, 2+hsel, 4+hsel}; p is uniform
// across its 16 lanes, so sm needs no cross-lane reduction.
__global__ void k_attn(const float* __restrict__ bias, int to_h2) {
    int w = blockIdx.x * (blockDim.x >> 5) + (threadIdx.x >> 5);
    if (w >= NN) return;
    float* out = to_h2 ? g_h2 : g_h1;
    int lane = threadIdx.x & 31;
    int n = w;
    int beg = g_off[n], end = g_off[n + 1];
    int hsel = lane >> 4;   // 0 or 1

    float adA = g_ad[n * HH + hsel];
    float adB = g_ad[n * HH + 2 + hsel];
    float adC = g_ad[n * HH + 4 + hsel];

    float smA = 0.f, smB = 0.f, smC = 0.f;
    float4 acc0 = make_float4(0, 0, 0, 0), acc1 = acc0, acc2 = acc0;

    int i = beg;
    for (; i + 4 <= end; i += 4) {
        int s[4];
#pragma unroll
        for (int u = 0; u < 4; u++) s[u] = g_srcs[i + u];
        float pA[4], pB[4], pC[4];
#pragma unroll
        for (int u = 0; u < 4; u++) {
            const float* as = g_as + s[u] * HH;
            pA[u] = leaky_exp(as[hsel]     + adA);
            pB[u] = leaky_exp(as[2 + hsel] + adB);
            pC[u] = leaky_exp(as[4 + hsel] + adC);
            smA += pA[u]; smB += pB[u]; smC += pC[u];
        }
#pragma unroll
        for (int u = 0; u < 4; u++) {
            const uint2* xs = g_xph + (size_t)s[u] * 96;
            uint2 v0 = xs[lane], v1 = xs[lane + 32], v2 = xs[lane + 64];
            acc_h4(acc0, pA[u], v0);
            acc_h4(acc1, pB[u], v1);
            acc_h4(acc2, pC[u], v2);
        }
    }
    for (; i < end; i++) {
        int s = g_srcs[i];
        const float* as = g_as + s * HH;
        float pA = leaky_exp(as[hsel]     + adA);
        float pB = leaky_exp(as[2 + hsel] + adB);
        float pC = leaky_exp(as[4 + hsel] + adC);
        smA += pA; smB += pB; smC += pC;
        const uint2* xs = g_xph + (size_t)s * 96;
        uint2 v0 = xs[lane], v1 = xs[lane + 32], v2 = xs[lane + 64];
        acc_h4(acc0, pA, v0);
        acc_h4(acc1, pB, v1);
        acc_h4(acc2, pC, v2);
    }

    // normalize per head before head-pair combine
    float iA = 1.f / (smA + 1e-16f);
    float iB = 1.f / (smB + 1e-16f);
    float iC = 1.f / (smC + 1e-16f);
    acc0.x *= iA; acc0.y *= iA; acc0.z *= iA; acc0.w *= iA;
    acc1.x *= iB; acc1.y *= iB; acc1.z *= iB; acc1.w *= iB;
    acc2.x *= iC; acc2.y *= iC; acc2.z *= iC; acc2.w *= iC;

    // head-pair sum (lane, lane^16 hold heads 2r, 2r+1 at same d)
    acc0.x += __shfl_xor_sync(0xffffffffu, acc0.x, 16);
    acc0.y += __shfl_xor_sync(0xffffffffu, acc0.y, 16);
    acc0.z += __shfl_xor_sync(0xffffffffu, acc0.z, 16);
    acc0.w += __shfl_xor_sync(0xffffffffu, acc0.w, 16);
    acc1.x += __shfl_xor_sync(0xffffffffu, acc1.x, 16);
    acc1.y += __shfl_xor_sync(0xffffffffu, acc1.y, 16);
    acc1.z += __shfl_xor_sync(0xffffffffu, acc1.z, 16);
    acc1.w += __shfl_xor_sync(0xffffffffu, acc1.w, 16);
    acc2.x += __shfl_xor_sync(0xffffffffu, acc2.x, 16);
    acc2.y += __shfl_xor_sync(0xffffffffu, acc2.y, 16);
    acc2.z += __shfl_xor_sync(0xffffffffu, acc2.z, 16);
    acc2.w += __shfl_xor_sync(0xffffffffu, acc2.w, 16);
    if (lane < 16) {
        float4 bv = *(const float4*)(bias + lane * 4);
        float4 o4;
        const float s6 = 1.f / 6.f;
        o4.x = (acc0.x + acc1.x + acc2.x) * s6 + bv.x;
        o4.y = (acc0.y + acc1.y + acc2.y) * s6 + bv.y;
        o4.z = (acc0.z + acc1.z + acc2.z) * s6 + bv.z;
        o4.w = (acc0.w + acc1.w + acc2.w) * s6 + bv.w;
        *(float4*)(out + n * DD + lane * 4) = o4;
    }
}

// ---------------------------------------------------------------- i_pool = item @ h2 (tiled, f32x2, split-K)
// block: 64 rows (batch) x 64 cols (D), K chunked by 32; grid (16, KSPLIT)
__global__ void k_pool(const float* __restrict__ item) {
    __shared__ float AsT[32][68];   // [k][m] item tile transposed
    __shared__ float Bs[32][68];    // [k][n] h2 tile
    int t = threadIdx.x;
    int m0 = blockIdx.x * 64;
    int kbase = blockIdx.y * KPB;
    int kend = kbase + KPB;
    int ty = t >> 4, tx = t & 15;
    int lk = t & 31, lm = t >> 5;
    float2 acc[4][2] = {};
    for (int k0 = kbase; k0 < kend; k0 += 32) {
        bool kv = (k0 + lk) < kend;
#pragma unroll
        for (int mm = lm; mm < 64; mm += 8)
            AsT[lk][mm] = kv ? item[(size_t)(m0 + mm) * NN + k0 + lk] : 0.f;
#pragma unroll
        for (int p = 0; p < 2; p++) {
            int q = t + p * 256;
            int kk = q >> 4, n4 = q & 15;
            float4 vv = ((k0 + kk) < kend) ? *(const float4*)(g_h2 + (size_t)(k0 + kk) * DD + n4 * 4)
                                           : make_float4(0, 0, 0, 0);
            *(float4*)&Bs[kk][n4 * 4] = vv;
        }
        __syncthreads();
#pragma unroll
        for (int k = 0; k < 32; k++) {
            float4 a4 = *(const float4*)&AsT[k][ty * 4];
            float4 b4 = *(const float4*)&Bs[k][tx * 4];
            float2 b01 = make_float2(b4.x, b4.y), b23 = make_float2(b4.z, b4.w);
            float a[4] = {a4.x, a4.y, a4.z, a4.w};
#pragma unroll
            for (int i = 0; i < 4; i++) {
                float2 ai = make_float2(a[i], a[i]);
                acc[i][0] = ffma2(acc[i][0], ai, b01);
                acc[i][1] = ffma2(acc[i][1], ai, b23);
            }
        }
        __syncthreads();
    }
#pragma unroll
    for (int i = 0; i < 4; i++) {
        int m = m0 + ty * 4 + i;
        atomicAdd(&g_pool[m * DD + tx * 4 + 0], acc[i][0].x);
        atomicAdd(&g_pool[m * DD + tx * 4 + 1], acc[i][0].y);
        atomicAdd(&g_pool[m * DD + tx * 4 + 2], acc[i][1].x);
        atomicAdd(&g_pool[m * DD + tx * 4 + 3], acc[i][1].y);
    }
}

// ---------------------------------------------------------------- fold MLP: w_eff = W0 @ W1, b_eff = b0.W1 + b1
__global__ void k_weff(const float* __restrict__ W0, const float* __restrict__ b0,
                       const float* __restrict__ W1, const float* __restrict__ b1) {
    __shared__ float sh[128];
    int t = threadIdx.x;
    float s = 0.f;
    for (int o = 0; o < 128; o++) s += W0[t * 128 + o] * W1[o];
    g_weff[t] = s;
    sh[t] = b0[t] * W1[t];
    __syncthreads();
    for (int st = 64; st > 0; st >>= 1) {
        if (t < st) sh[t] += sh[t + st];
        __syncthreads();
    }
    if (t == 0) g_beff = sh[0] + b1[0];
}

// ---------------------------------------------------------------- final: sigmoid(concat(u_emb,i_pool) . w_eff + b_eff)
__global__ void k_final(const int* __restrict__ user, const float* __restrict__ utab,
                        float* __restrict__ out) {
    int w = (blockIdx.x * blockDim.x + threadIdx.x) >> 5;
    if (w >= BB) return;
    int lane = threadIdx.x & 31;
    int u = user[w];
    float a = 0.f;
#pragma unroll
    for (int j = 0; j < 4; j++) {
        int dim = lane * 4 + j;
        float v = (dim < DD) ? utab[u * DD + dim] : g_pool[w * DD + dim - DD];
        a += v * g_weff[dim];
    }
    for (int o = 16; o; o >>= 1) a += __shfl_down_sync(0xffffffffu, a, o);
    if (lane == 0) out[w] = 1.f / (1.f + __expf(-(a + g_beff)));
}

// ================================================================ launch
extern "C" void kernel_launch(void* const* d_in, const int* in_sizes, int n_in,
                              void* d_out, int out_size) {
    const int*   user = (const int*)d_in[0];
    const float* item = (const float*)d_in[1];
    const int*   ei   = (const int*)d_in[3];
    const float* utab = (const float*)d_in[4];
    const float* itab = (const float*)d_in[5];
    const float* W0g  = (const float*)d_in[6];
    const float* as0  = (const float*)d_in[7];
    const float* ad0  = (const float*)d_in[8];
    const float* b0g  = (const float*)d_in[9];
    const float* W1g  = (const float*)d_in[10];
    const float* as1  = (const float*)d_in[11];
    const float* ad1  = (const float*)d_in[12];
    const float* b1g  = (const float*)d_in[13];
    const float* lW0  = (const float*)d_in[14];
    const float* lb0  = (const float*)d_in[15];
    const float* lW1  = (const float*)d_in[16];
    const float* lb1  = (const float*)d_in[17];
    float* out = (float*)d_out;

    k_init<<<256, 256>>>();
    k_hist<<<(NE + 255) / 256, 256>>>(ei);
    k_scan<<<1, 1024>>>();
    k_fill<<<(ET + 255) / 256, 256>>>(ei);

    // layer 0
    k_gemm<<<dim3((NN + 63) / 64, 6), 256>>>(itab, W0g, as0, ad0, 0);
    k_attn<<<(NN + 7) / 8, 256>>>(b0g, 0);

    // layer 1
    k_gemm<<<dim3((NN + 63) / 64, 6), 256>>>(nullptr, W1g, as1, ad1, 1);
    k_attn<<<(NN + 7) / 8, 256>>>(b1g, 1);

    // pooling + head
    k_pool<<<dim3(BB / 64, KSPLIT), 256>>>(item);
    k_weff<<<1, 128>>>(lW0, lb0, lW1, lb1);
    k_final<<<BB * 32 / 256, 256>>>(user, utab, out);
}

// round 13
// speedup vs baseline: 1.6061x; 1.6061x over previous
#include <cuda_runtime.h>
#include <cuda_fp16.h>

#define NN 50000
#define NE 800000
#define ET 850000   // NE + NN self loops
#define DD 64
#define HH 6
#define HD 384      // HH*DD
#define BB 1024
#define KSPLIT 37   // 16*37 = 592 blocks = exactly 4 per SM (148 SMs)
#define KPB ((NN + KSPLIT - 1) / KSPLIT)   // 1352

// ---- scratch (device globals; no allocation allowed) ----
__device__ uint2 g_xph[NN * 96];     // per-layer transformed features [N,H*D] as fp16 (4 halves per uint2)
__device__ float g_as[NN * HH];
__device__ float g_ad[NN * HH];
__device__ float g_h1[NN * DD];      // layer-0 output
__device__ float g_h2[NN * DD];      // layer-1 output
__device__ float g_pool[BB * DD];
__device__ float g_weff[2 * DD];
__device__ float g_beff;
__device__ int   g_deg[NN];
__device__ int   g_off[NN + 1];
__device__ int   g_cur[NN];
__device__ int   g_srcs[ET];

// packed f32x2 FMA (sm_100+ FFMA2)
__device__ __forceinline__ float2 ffma2(float2 d, float2 a, float2 b) {
    unsigned long long dd = *reinterpret_cast<unsigned long long*>(&d);
    unsigned long long aa = *reinterpret_cast<unsigned long long*>(&a);
    unsigned long long bb = *reinterpret_cast<unsigned long long*>(&b);
    asm("fma.rn.f32x2 %0, %1, %2, %0;" : "+l"(dd) : "l"(aa), "l"(bb));
    return *reinterpret_cast<float2*>(&dd);
}

// ---------------------------------------------------------------- init
__global__ void k_init() {
    int i = blockIdx.x * blockDim.x + threadIdx.x;
    if (i < NN) g_deg[i] = 1;              // self loop
    if (i < BB * DD) g_pool[i] = 0.f;
}

// ---------------------------------------------------------------- histogram of dst
__global__ void k_hist(const int* __restrict__ ei) {
    int e = blockIdx.x * blockDim.x + threadIdx.x;
    if (e < NE) atomicAdd(&g_deg[ei[NE + e]], 1);
}

// ---------------------------------------------------------------- exclusive scan (1 block, warp shuffles)
__global__ void k_scan() {
    const int C = 49;                      // 1024*49 >= NN
    int t = threadIdx.x;
    int base = t * C;
    int v[C];
    int run = 0;
#pragma unroll
    for (int i = 0; i < C; i++) {
        int idx = base + i;
        int d = (idx < NN) ? g_deg[idx] : 0;
        run += d;
        v[i] = run;                        // inclusive within chunk
    }
    int lane = t & 31, wid = t >> 5;
    int x = run;
#pragma unroll
    for (int o = 1; o < 32; o <<= 1) {
        int y = __shfl_up_sync(0xffffffffu, x, o);
        if (lane >= o) x += y;
    }
    __shared__ int wsum[32];
    if (lane == 31) wsum[wid] = x;
    __syncthreads();
    if (wid == 0) {
        int w = wsum[lane];
#pragma unroll
        for (int o = 1; o < 32; o <<= 1) {
            int y = __shfl_up_sync(0xffffffffu, w, o);
            if (lane >= o) w += y;
        }
        wsum[lane] = w;
    }
    __syncthreads();
    int prefix = x - run + (wid ? wsum[wid - 1] : 0);  // exclusive prefix of chunk
    if (t == 0) g_off[0] = 0;
#pragma unroll
    for (int i = 0; i < C; i++) {
        int idx = base + i;
        if (idx < NN) {
            g_off[idx + 1] = prefix + v[i];
            g_cur[idx] = prefix + (i ? v[i - 1] : 0);
        }
    }
}

// ---------------------------------------------------------------- fill CSR (srcs grouped by dst)
__global__ void k_fill(const int* __restrict__ ei) {
    int i = blockIdx.x * blockDim.x + threadIdx.x;
    if (i >= ET) return;
    int s, d;
    if (i < NE) { s = ei[i]; d = ei[NE + i]; }
    else        { s = i - NE; d = s; }
    int pos = atomicAdd(&g_cur[d], 1);
    g_srcs[pos] = s;
}

// ---------------------------------------------------------------- xp = x @ W + fused attention dots
// block: 64 rows x 64 cols; blockIdx.y == head h (cols are exactly head h)
// xp stored as fp16 (only consumer is the attn gather)
__global__ void k_gemm(const float* __restrict__ x_in, const float* __restrict__ W,
                       const float* __restrict__ asrc, const float* __restrict__ adst,
                       int use_h1) {
    __shared__ float AsT[64][68];   // [k][row]
    __shared__ float Bs[64][68];    // [k][col]
    const float* x = use_h1 ? g_h1 : x_in;
    int t = threadIdx.x;
    int row0 = blockIdx.x * 64;
    int h = blockIdx.y;
    int col0 = h * 64;
    {
        int lr = t >> 4, lc = (t & 15) * 4;
#pragma unroll
        for (int r = lr; r < 64; r += 16) {
            int gr = row0 + r;
            float4 v = (gr < NN) ? *(const float4*)(x + (size_t)gr * DD + lc)
                                 : make_float4(0, 0, 0, 0);
            AsT[lc][r] = v.x; AsT[lc + 1][r] = v.y; AsT[lc + 2][r] = v.z; AsT[lc + 3][r] = v.w;
        }
#pragma unroll
        for (int k = lr; k < 64; k += 16) {
            float4 v = *(const float4*)(W + (size_t)k * HD + col0 + lc);
            Bs[k][lc] = v.x; Bs[k][lc + 1] = v.y; Bs[k][lc + 2] = v.z; Bs[k][lc + 3] = v.w;
        }
    }
    __syncthreads();
    int ty = t >> 4, tx = t & 15;
    float2 acc[4][2] = {};
#pragma unroll
    for (int k = 0; k < 64; k++) {
        float4 a4 = *(const float4*)&AsT[k][ty * 4];
        float4 b4 = *(const float4*)&Bs[k][tx * 4];
        float2 b01 = make_float2(b4.x, b4.y), b23 = make_float2(b4.z, b4.w);
        float a[4] = {a4.x, a4.y, a4.z, a4.w};
#pragma unroll
        for (int i = 0; i < 4; i++) {
            float2 ai = make_float2(a[i], a[i]);
            acc[i][0] = ffma2(acc[i][0], ai, b01);
            acc[i][1] = ffma2(acc[i][1], ai, b23);
        }
    }
    // epilogue: write xp (fp16) and fused as/ad dot-products for head h
    float4 sa4 = *(const float4*)(asrc + col0 + tx * 4);
    float4 sd4 = *(const float4*)(adst + col0 + tx * 4);
#pragma unroll
    for (int i = 0; i < 4; i++) {
        int gr = row0 + ty * 4 + i;
        float4 o = make_float4(acc[i][0].x, acc[i][0].y, acc[i][1].x, acc[i][1].y);
        if (gr < NN) {
            __half2 h01 = __floats2half2_rn(o.x, o.y);
            __half2 h23 = __floats2half2_rn(o.z, o.w);
            uint2 u;
            u.x = *reinterpret_cast<unsigned int*>(&h01);
            u.y = *reinterpret_cast<unsigned int*>(&h23);
            g_xph[(size_t)gr * 96 + h * 16 + tx] = u;
        }
        float s1 = o.x * sa4.x + o.y * sa4.y + o.z * sa4.z + o.w * sa4.w;
        float s2 = o.x * sd4.x + o.y * sd4.y + o.z * sd4.z + o.w * sd4.w;
#pragma unroll
        for (int m = 8; m; m >>= 1) {
            s1 += __shfl_xor_sync(0xffffffffu, s1, m);
            s2 += __shfl_xor_sync(0xffffffffu, s2, m);
        }
        if (tx == 0 && gr < NN) { g_as[gr * HH + h] = s1; g_ad[gr * HH + h] = s2; }
    }
}

// unpack 4 halves (uint2) and accumulate with weight w
__device__ __forceinline__ void acc_h4(float4& acc, float w, uint2 v) {
    __half2 a = *reinterpret_cast<__half2*>(&v.x);
    __half2 b = *reinterpret_cast<__half2*>(&v.y);
    float2 f01 = __half22float2(a);
    float2 f23 = __half22float2(b);
    acc.x += w * f01.x; acc.y += w * f01.y;
    acc.z += w * f23.x; acc.w += w * f23.y;
}

__device__ __forceinline__ float leaky_exp(float e) {
    e = (e > 0.f) ? e : 0.2f * e;
    return __expf(e);
}

// ---------------------------------------------------------------- attention: warp per dst node, SINGLE PASS
// softmax shift-invariance (no max) + post-normalization; unroll x8 for deep MLP
// (24 LDG.64 gathers in flight per batch vs exposed L2 latency)
__global__ void k_attn(const float* __restrict__ bias, int to_h2) {
    int w = blockIdx.x * (blockDim.x >> 5) + (threadIdx.x >> 5);
    if (w >= NN) return;
    float* out = to_h2 ? g_h2 : g_h1;
    int lane = threadIdx.x & 31;
    int n = w;
    int beg = g_off[n], end = g_off[n + 1];
    int hsel = lane >> 4;   // 0 or 1

    float adA = g_ad[n * HH + hsel];
    float adB = g_ad[n * HH + 2 + hsel];
    float adC = g_ad[n * HH + 4 + hsel];

    float smA = 0.f, smB = 0.f, smC = 0.f;
    float4 acc0 = make_float4(0, 0, 0, 0), acc1 = acc0, acc2 = acc0;

    int i = beg;
    for (; i + 8 <= end; i += 8) {
        int s[8];
#pragma unroll
        for (int u = 0; u < 8; u++) s[u] = g_srcs[i + u];
        float pA[8], pB[8], pC[8];
#pragma unroll
        for (int u = 0; u < 8; u++) {
            const float* as = g_as + s[u] * HH;
            pA[u] = leaky_exp(as[hsel]     + adA);
            pB[u] = leaky_exp(as[2 + hsel] + adB);
            pC[u] = leaky_exp(as[4 + hsel] + adC);
            smA += pA[u]; smB += pB[u]; smC += pC[u];
        }
#pragma unroll
        for (int u = 0; u < 8; u++) {
            const uint2* xs = g_xph + (size_t)s[u] * 96;
            uint2 v0 = xs[lane], v1 = xs[lane + 32], v2 = xs[lane + 64];
            acc_h4(acc0, pA[u], v0);
            acc_h4(acc1, pB[u], v1);
            acc_h4(acc2, pC[u], v2);
        }
    }
    for (; i < end; i++) {
        int s = g_srcs[i];
        const float* as = g_as + s * HH;
        float pA = leaky_exp(as[hsel]     + adA);
        float pB = leaky_exp(as[2 + hsel] + adB);
        float pC = leaky_exp(as[4 + hsel] + adC);
        smA += pA; smB += pB; smC += pC;
        const uint2* xs = g_xph + (size_t)s * 96;
        uint2 v0 = xs[lane], v1 = xs[lane + 32], v2 = xs[lane + 64];
        acc_h4(acc0, pA, v0);
        acc_h4(acc1, pB, v1);
        acc_h4(acc2, pC, v2);
    }

    // normalize per head before head-pair combine
    float iA = 1.f / (smA + 1e-16f);
    float iB = 1.f / (smB + 1e-16f);
    float iC = 1.f / (smC + 1e-16f);
    acc0.x *= iA; acc0.y *= iA; acc0.z *= iA; acc0.w *= iA;
    acc1.x *= iB; acc1.y *= iB; acc1.z *= iB; acc1.w *= iB;
    acc2.x *= iC; acc2.y *= iC; acc2.z *= iC; acc2.w *= iC;

    // head-pair sum (lane, lane^16 hold heads 2r, 2r+1 at same d)
    acc0.x += __shfl_xor_sync(0xffffffffu, acc0.x, 16);
    acc0.y += __shfl_xor_sync(0xffffffffu, acc0.y, 16);
    acc0.z += __shfl_xor_sync(0xffffffffu, acc0.z, 16);
    acc0.w += __shfl_xor_sync(0xffffffffu, acc0.w, 16);
    acc1.x += __shfl_xor_sync(0xffffffffu, acc1.x, 16);
    acc1.y += __shfl_xor_sync(0xffffffffu, acc1.y, 16);
    acc1.z += __shfl_xor_sync(0xffffffffu, acc1.z, 16);
    acc1.w += __shfl_xor_sync(0xffffffffu, acc1.w, 16);
    acc2.x += __shfl_xor_sync(0xffffffffu, acc2.x, 16);
    acc2.y += __shfl_xor_sync(0xffffffffu, acc2.y, 16);
    acc2.z += __shfl_xor_sync(0xffffffffu, acc2.z, 16);
    acc2.w += __shfl_xor_sync(0xffffffffu, acc2.w, 16);
    if (lane < 16) {
        float4 bv = *(const float4*)(bias + lane * 4);
        float4 o4;
        const float s6 = 1.f / 6.f;
        o4.x = (acc0.x + acc1.x + acc2.x) * s6 + bv.x;
        o4.y = (acc0.y + acc1.y + acc2.y) * s6 + bv.y;
        o4.z = (acc0.z + acc1.z + acc2.z) * s6 + bv.z;
        o4.w = (acc0.w + acc1.w + acc2.w) * s6 + bv.w;
        *(float4*)(out + n * DD + lane * 4) = o4;
    }
}

// ---------------------------------------------------------------- i_pool = item @ h2 (tiled, f32x2, split-K)
// block: 64 rows (batch) x 64 cols (D), K chunked by 32; grid (16, KSPLIT=37) = 592 blocks = 4/SM
__global__ void k_pool(const float* __restrict__ item) {
    __shared__ float AsT[32][68];   // [k][m] item tile transposed
    __shared__ float Bs[32][68];    // [k][n] h2 tile
    int t = threadIdx.x;
    int m0 = blockIdx.x * 64;
    int kbase = blockIdx.y * KPB;
    int kend = kbase + KPB;
    if (kend > NN) kend = NN;
    int ty = t >> 4, tx = t & 15;
    int lk = t & 31, lm = t >> 5;
    float2 acc[4][2] = {};
    for (int k0 = kbase; k0 < kend; k0 += 32) {
        bool kv = (k0 + lk) < kend;
#pragma unroll
        for (int mm = lm; mm < 64; mm += 8)
            AsT[lk][mm] = kv ? item[(size_t)(m0 + mm) * NN + k0 + lk] : 0.f;
#pragma unroll
        for (int p = 0; p < 2; p++) {
            int q = t + p * 256;
            int kk = q >> 4, n4 = q & 15;
            float4 vv = ((k0 + kk) < kend) ? *(const float4*)(g_h2 + (size_t)(k0 + kk) * DD + n4 * 4)
                                           : make_float4(0, 0, 0, 0);
            *(float4*)&Bs[kk][n4 * 4] = vv;
        }
        __syncthreads();
#pragma unroll
        for (int k = 0; k < 32; k++) {
            float4 a4 = *(const float4*)&AsT[k][ty * 4];
            float4 b4 = *(const float4*)&Bs[k][tx * 4];
            float2 b01 = make_float2(b4.x, b4.y), b23 = make_float2(b4.z, b4.w);
            float a[4] = {a4.x, a4.y, a4.z, a4.w};
#pragma unroll
            for (int i = 0; i < 4; i++) {
                float2 ai = make_float2(a[i], a[i]);
                acc[i][0] = ffma2(acc[i][0], ai, b01);
                acc[i][1] = ffma2(acc[i][1], ai, b23);
            }
        }
        __syncthreads();
    }
#pragma unroll
    for (int i = 0; i < 4; i++) {
        int m = m0 + ty * 4 + i;
        atomicAdd(&g_pool[m * DD + tx * 4 + 0], acc[i][0].x);
        atomicAdd(&g_pool[m * DD + tx * 4 + 1], acc[i][0].y);
        atomicAdd(&g_pool[m * DD + tx * 4 + 2], acc[i][1].x);
        atomicAdd(&g_pool[m * DD + tx * 4 + 3], acc[i][1].y);
    }
}

// ---------------------------------------------------------------- fold MLP: w_eff = W0 @ W1, b_eff = b0.W1 + b1
__global__ void k_weff(const float* __restrict__ W0, const float* __restrict__ b0,
                       const float* __restrict__ W1, const float* __restrict__ b1) {
    __shared__ float sh[128];
    int t = threadIdx.x;
    float s = 0.f;
    for (int o = 0; o < 128; o++) s += W0[t * 128 + o] * W1[o];
    g_weff[t] = s;
    sh[t] = b0[t] * W1[t];
    __syncthreads();
    for (int st = 64; st > 0; st >>= 1) {
        if (t < st) sh[t] += sh[t + st];
        __syncthreads();
    }
    if (t == 0) g_beff = sh[0] + b1[0];
}

// ---------------------------------------------------------------- final: sigmoid(concat(u_emb,i_pool) . w_eff + b_eff)
__global__ void k_final(const int* __restrict__ user, const float* __restrict__ utab,
                        float* __restrict__ out) {
    int w = (blockIdx.x * blockDim.x + threadIdx.x) >> 5;
    if (w >= BB) return;
    int lane = threadIdx.x & 31;
    int u = user[w];
    float a = 0.f;
#pragma unroll
    for (int j = 0; j < 4; j++) {
        int dim = lane * 4 + j;
        float v = (dim < DD) ? utab[u * DD + dim] : g_pool[w * DD + dim - DD];
        a += v * g_weff[dim];
    }
    for (int o = 16; o; o >>= 1) a += __shfl_down_sync(0xffffffffu, a, o);
    if (lane == 0) out[w] = 1.f / (1.f + __expf(-(a + g_beff)));
}

// ================================================================ launch
extern "C" void kernel_launch(void* const* d_in, const int* in_sizes, int n_in,
                              void* d_out, int out_size) {
    const int*   user = (const int*)d_in[0];
    const float* item = (const float*)d_in[1];
    const int*   ei   = (const int*)d_in[3];
    const float* utab = (const float*)d_in[4];
    const float* itab = (const float*)d_in[5];
    const float* W0g  = (const float*)d_in[6];
    const float* as0  = (const float*)d_in[7];
    const float* ad0  = (const float*)d_in[8];
    const float* b0g  = (const float*)d_in[9];
    const float* W1g  = (const float*)d_in[10];
    const float* as1  = (const float*)d_in[11];
    const float* ad1  = (const float*)d_in[12];
    const float* b1g  = (const float*)d_in[13];
    const float* lW0  = (const float*)d_in[14];
    const float* lb0  = (const float*)d_in[15];
    const float* lW1  = (const float*)d_in[16];
    const float* lb1  = (const float*)d_in[17];
    float* out = (float*)d_out;

    k_init<<<256, 256>>>();
    k_hist<<<(NE + 255) / 256, 256>>>(ei);
    k_scan<<<1, 1024>>>();
    k_fill<<<(ET + 255) / 256, 256>>>(ei);

    // layer 0
    k_gemm<<<dim3((NN + 63) / 64, 6), 256>>>(itab, W0g, as0, ad0, 0);
    k_attn<<<(NN + 7) / 8, 256>>>(b0g, 0);

    // layer 1
    k_gemm<<<dim3((NN + 63) / 64, 6), 256>>>(nullptr, W1g, as1, ad1, 1);
    k_attn<<<(NN + 7) / 8, 256>>>(b1g, 1);

    // pooling + head
    k_pool<<<dim3(BB / 64, KSPLIT), 256>>>(item);
    k_weff<<<1, 128>>>(lW0, lb0, lW1, lb1);
    k_final<<<BB * 32 / 256, 256>>>(user, utab, out);
}